// round 9
// baseline (speedup 1.0000x reference)
#include <cuda_runtime.h>
#include <math.h>

#define EPS 1e-8f
#define LN_EPS 1e-5f
#define CHUNK 32

// ---------------- scratch (static __device__, no allocs) ----------------
__device__ __align__(16) float  g_q[16*512*64];
__device__ __align__(16) float  g_z[16*512*64];
__device__ __align__(16) float  g_v[16*512*64];
__device__ __align__(16) float  g_part[16*16*4160];
__device__ float4 g_pack[16*4096];      // {sg, sb+Ps_ln, ng, nb+Mprev_ln}
__device__ float  g_Pz[16*64];          // P_z_ln last step per batch
__device__ double g_acc[2];             // sum, sumsq for std

__device__ __forceinline__ float eluf(float x){ return x > 0.f ? x : (expf(x) - 1.f); }

// one-sync block reduce for 256 threads (8 warps). Results broadcast to ALL
// threads in out[]. red: >= 8*N floats; must not be rewritten until a
// block-wide sync after return (alternate buffers for back-to-back calls).
template<int N>
__device__ __forceinline__ void block_reduce_b(const float* v, float* red, float* out){
    int lane = threadIdx.x & 31, w = threadIdx.x >> 5;
    #pragma unroll
    for (int i = 0; i < N; i++){
        float x = v[i];
        #pragma unroll
        for (int o = 16; o; o >>= 1) x += __shfl_xor_sync(0xffffffffu, x, o);
        if (lane == 0) red[w*N + i] = x;
    }
    __syncthreads();
    #pragma unroll
    for (int i = 0; i < N; i++){
        float s = 0.f;
        #pragma unroll
        for (int ww2 = 0; ww2 < 8; ww2++) s += red[ww2*N + i];
        out[i] = s;
    }
}

// ---------------- fused front kernel: phase1 GEMMs (blocks [0,B*NCH)) +
// ---------------- prompt/history precompute (blocks [B*NCH, B*NCH+B)) ----
__global__ __launch_bounds__(256)
void k_front(const int* uid, const float* X, const float* Pm, const float* Sm,
             const float* Wq, const float* bq, const float* Wk, const float* bk,
             const float* Wv, const float* bv,
             const float* zg, const float* zb, const float* sg, const float* sb,
             const float* ng, const float* nb,
             const float* pzbuf, const float* psbuf, int NCH, int LP, int NPH)
{
    __shared__ __align__(16) float SBUF[11360];
    int tid = threadIdx.x;

    if ((int)blockIdx.x < NPH){
        // ---------------- phase1 branch ----------------
        float* xsT  = SBUF;            // 64*36 transposed X chunk
        float* zbuf = SBUF + 2304;     // 32*64
        float* vbuf = SBUF + 4352;     // 32*64

        int b = blockIdx.x / NCH, ch = blockIdx.x % NCH;
        int L = NCH * CHUNK;
        size_t xbase = ((size_t)b*L + (size_t)ch*CHUNK) * 64;

        #pragma unroll
        for (int i = 0; i < 8; i++){
            int e = tid + i*256;
            int l = e >> 6, k = e & 63;
            xsT[k*36 + l] = X[xbase + e];
        }
        __syncthreads();

        // all 256 threads: thread = (row-group of 8, col); computes q,z,v
        {
            int col = tid & 63, grp = tid >> 6;   // grp 0..3 -> rows grp*8..grp*8+7
            float aq[8], az[8], av[8];
            float b0 = bq[col], b1 = bk[col], b2 = bv[col];
            #pragma unroll
            for (int l = 0; l < 8; l++){ aq[l] = b0; az[l] = b1; av[l] = b2; }
            #pragma unroll 4
            for (int k = 0; k < 64; k++){
                float wqv = Wq[k*64 + col];
                float wkv = Wk[k*64 + col];
                float wvv = Wv[k*64 + col];
                const float4* xr = (const float4*)&xsT[k*36 + grp*8];
                float4 x0 = xr[0], x1 = xr[1];
                float xv[8] = {x0.x, x0.y, x0.z, x0.w, x1.x, x1.y, x1.z, x1.w};
                #pragma unroll
                for (int l = 0; l < 8; l++){
                    aq[l] = fmaf(xv[l], wqv, aq[l]);
                    az[l] = fmaf(xv[l], wkv, az[l]);
                    av[l] = fmaf(xv[l], wvv, av[l]);
                }
            }
            #pragma unroll
            for (int l = 0; l < 8; l++){
                int row = grp*8 + l;
                g_q[xbase + row*64 + col] = eluf(aq[l]);
                float zv = eluf(az[l]);
                zbuf[row*64 + col] = zv;
                g_z[xbase + row*64 + col] = zv;
                vbuf[row*64 + col] = av[l];
                g_v[xbase + row*64 + col] = av[l];
            }
        }
        __syncthreads();

        int p = tid & 63, d0 = (tid >> 6) * 16;
        float acc[16];
        #pragma unroll
        for (int i = 0; i < 16; i++) acc[i] = 0.f;
        #pragma unroll 4
        for (int l = 0; l < 32; l++){
            float vv = vbuf[l*64 + p];
            const float4* zb4 = (const float4*)&zbuf[l*64 + d0];
            #pragma unroll
            for (int j = 0; j < 4; j++){
                float4 z4 = zb4[j];
                acc[j*4+0] = fmaf(z4.x, vv, acc[j*4+0]);
                acc[j*4+1] = fmaf(z4.y, vv, acc[j*4+1]);
                acc[j*4+2] = fmaf(z4.z, vv, acc[j*4+2]);
                acc[j*4+3] = fmaf(z4.w, vv, acc[j*4+3]);
            }
        }
        size_t o = (size_t)(b*NCH + ch) * 4160;
        #pragma unroll
        for (int i = 0; i < 16; i++) g_part[o + (d0 + i)*64 + p] = acc[i];
        if (tid < 64){
            float zs = 0.f;
            #pragma unroll 4
            for (int l = 0; l < 32; l++) zs += zbuf[l*64 + tid];
            g_part[o + 4096 + tid] = zs;
        }
        return;
    }

    // ---------------- prompt branch ----------------
    float* xsA  = SBUF;          float* xsB  = SBUF + 512;
    float* zbA  = SBUF + 1024;   float* zbB  = SBUF + 1536;
    float* vbA  = SBUF + 2048;   float* vbB  = SBUF + 2560;
    float* bufA = SBUF + 3072;   float* bufB = SBUF + 7168;
    float* zl   = SBUF + 11264;
    float* redA = SBUF + 11328;  float* redB = SBUF + 11344;

    int b = blockIdx.x - NPH;
    int p = tid & 63, d0 = (tid >> 6) * 16;

    if (b == 0 && tid == 0){ g_acc[0] = 0.0; g_acc[1] = 0.0; }

    for (int i = tid; i < 512; i += 256){ xsA[i] = 0.f; xsB[i] = 0.f; }
    for (int i = tid; i < LP*64; i += 256){
        xsA[i] = Pm[b*LP*64 + i];
        xsB[i] = Sm[b*LP*64 + i];
    }
    __syncthreads();

    {
        int pass = tid >> 7, dt = (tid >> 6) & 1, col = tid & 63;
        const float* xp = pass ? xsB : xsA;
        float* zp = pass ? zbB : zbA;
        float* vp = pass ? vbB : vbA;
        const float* W  = dt ? Wv : Wk;
        float bb = dt ? bv[col] : bk[col];
        float acc8[8];
        #pragma unroll
        for (int l = 0; l < 8; l++) acc8[l] = bb;
        #pragma unroll 4
        for (int k = 0; k < 64; k++){
            float w = W[k*64 + col];
            #pragma unroll
            for (int l = 0; l < 8; l++) acc8[l] += xp[l*64 + k] * w;
        }
        if (dt == 0){
            #pragma unroll
            for (int l = 0; l < 8; l++) zp[l*64 + col] = eluf(acc8[l]);
        } else {
            #pragma unroll
            for (int l = 0; l < 8; l++) vp[l*64 + col] = acc8[l];
        }
    }
    __syncthreads();

    float accP[16], accS[16];
    #pragma unroll
    for (int i = 0; i < 16; i++){ accP[i] = 0.f; accS[i] = 0.f; }
    for (int l = 0; l < LP; l++){
        float vvP = vbA[l*64 + p], vvS = vbB[l*64 + p];
        #pragma unroll
        for (int i = 0; i < 16; i++){
            accP[i] += zbA[l*64 + d0 + i] * vvP;
            accS[i] += zbB[l*64 + d0 + i] * vvS;
        }
    }
    float zsP = 0.f, zsS = 0.f;
    if (tid < 64){
        for (int l = 0; l < LP; l++){ zsP += zbA[l*64 + tid]; zsS += zbB[l*64 + tid]; }
    }

    float rv[2], out2[2];
    rv[0] = (tid < 64) ? zsP : 0.f; rv[1] = (tid < 64) ? zsP*zsP : 0.f;
    block_reduce_b<2>(rv, redA, out2);
    {
        float mz = out2[0]*(1.f/64.f);
        float ivz = rsqrtf(out2[1]*(1.f/64.f) - mz*mz + LN_EPS);
        if (tid < 64) g_Pz[b*64 + tid] = (zsP - mz)*ivz*zg[tid] + zb[tid];
    }
    rv[0] = (tid < 64) ? zsS : 0.f; rv[1] = (tid < 64) ? zsS*zsS : 0.f;
    block_reduce_b<2>(rv, redB, out2);
    {
        float mz = out2[0]*(1.f/64.f);
        float ivz = rsqrtf(out2[1]*(1.f/64.f) - mz*mz + LN_EPS);
        if (tid < 64) zl[tid] = (zsS - mz)*ivz*zg[tid] + zb[tid];
    }
    float sv[2];
    sv[0] = 0.f; sv[1] = 0.f;
    #pragma unroll
    for (int i = 0; i < 16; i++){ sv[0] += accP[i]; sv[1] += accP[i]*accP[i]; }
    block_reduce_b<2>(sv, redA, out2);
    {
        float ms = out2[0]*(1.f/4096.f);
        float ivs = rsqrtf(out2[1]*(1.f/4096.f) - ms*ms + LN_EPS);
        #pragma unroll
        for (int i = 0; i < 16; i++){
            int e = (d0 + i)*64 + p;
            bufA[e] = (accP[i] - ms)*ivs*sg[e] + sb[e];
        }
    }
    sv[0] = 0.f; sv[1] = 0.f;
    #pragma unroll
    for (int i = 0; i < 16; i++){ sv[0] += accS[i]; sv[1] += accS[i]*accS[i]; }
    block_reduce_b<2>(sv, redB, out2);
    {
        float ms = out2[0]*(1.f/4096.f);
        float ivs = rsqrtf(out2[1]*(1.f/4096.f) - ms*ms + LN_EPS);
        #pragma unroll
        for (int i = 0; i < 16; i++){
            int e = (d0 + i)*64 + p;
            bufB[e] = (accS[i] - ms)*ivs*sg[e] + sb[e];
        }
    }
    __syncthreads();

    int u = uid[b];
    float pzv = 0.f;
    if (tid < 64) pzv = pzbuf[(size_t)u*64 + tid] + zl[tid];
    float rv1[1], out1[1];
    rv1[0] = (tid < 64) ? pzv*pzv : 0.f;
    block_reduce_b<1>(rv1, redA, out1);
    float ipn = 1.f / (fmaxf(sqrtf(out1[0]), 1e-8f) + EPS);

    float pn16[16];
    sv[0] = 0.f; sv[1] = 0.f;
    #pragma unroll
    for (int k2 = 0; k2 < 16; k2++){
        int e = tid + k2*256;
        float pv = (psbuf[(size_t)u*4096 + e] + bufB[e]) * ipn;
        pn16[k2] = pv; sv[0] += pv; sv[1] += pv*pv;
    }
    block_reduce_b<2>(sv, redB, out2);
    float mp = out2[0]*(1.f/4096.f);
    float ivp = rsqrtf(out2[1]*(1.f/4096.f) - mp*mp + LN_EPS);
    #pragma unroll
    for (int k2 = 0; k2 < 16; k2++){
        int e = tid + k2*256;
        float M = (pn16[k2] - mp)*ivp*ng[e] + nb[e];
        g_pack[b*4096 + e] = make_float4(sg[e], sb[e] + bufA[e], ng[e], nb[e] + M);
    }
}

// ---------------- kernel D: main per-step scan.
// All per-element work (state update + 6 moment sums + 5 q-moment sums) runs
// BEFORE sync 1; after the reduce only ~25 scalar ops + 4 FMA remain.
__global__ __launch_bounds__(256, 2)
void k_main(const float* __restrict__ zg, const float* __restrict__ zb,
            const float* __restrict__ nag, const float* __restrict__ nab,
            float* __restrict__ out, int NCH)
{
    __shared__ __align__(16) float ztile[2048];
    __shared__ __align__(16) float vtile[2048];
    __shared__ __align__(16) float qtile[2048];
    __shared__ float4 red4[8][3];
    __shared__ float na_part[256];
    __shared__ float cred[64];
    __shared__ double db[128];

    int tid = threadIdx.x;
    int b = blockIdx.x / NCH, ch = blockIdx.x % NCH;
    int lane = tid & 31, w = tid >> 5;
    int p = tid & 63, d0 = (tid >> 6) * 16;
    int L = NCH * CHUNK;
    size_t base = ((size_t)b*L + (size_t)ch*CHUNK) * 64;

    // preload whole chunk z/v/q tiles (float4)
    {
        const float4* gz4 = (const float4*)(g_z + base);
        const float4* gv4 = (const float4*)(g_v + base);
        const float4* gq4 = (const float4*)(g_q + base);
        float4* zt4 = (float4*)ztile; float4* vt4 = (float4*)vtile; float4* qt4 = (float4*)qtile;
        #pragma unroll
        for (int i = 0; i < 2; i++){
            int e = tid + i*256;
            zt4[e] = gz4[e]; vt4[e] = gv4[e]; qt4[e] = gq4[e];
        }
    }
    // packed constants -> registers
    float wx[16], wy[16], wz[16], ww[16];
    {
        const float4* pk = &g_pack[b*4096];
        #pragma unroll
        for (int i = 0; i < 16; i++){
            float4 t = pk[(d0 + i)*64 + p];
            wx[i] = t.x; wy[i] = t.y; wz[i] = t.z; ww[i] = t.w;
        }
    }
    float zpxv = 0.f, zpyv = 0.f;
    if (tid < 64){ zpxv = zg[tid]; zpyv = zb[tid] + g_Pz[b*64 + tid]; }
    float ngA = 0.f, ngB = 0.f, nbA = 0.f, nbB = 0.f;
    if (tid < 32){ ngA = nag[lane]; ngB = nag[lane+32]; nbA = nab[lane]; nbB = nab[lane+32]; }

    // fused exclusive prefix over prior chunks' partials
    float A[16];
    #pragma unroll
    for (int i = 0; i < 16; i++) A[i] = 0.f;
    float zc = 0.f;
    for (int c2 = 0; c2 < ch; c2++){
        const float* gp = &g_part[(size_t)(b*NCH + c2) * 4160];
        #pragma unroll
        for (int i = 0; i < 16; i++) A[i] += gp[(d0 + i)*64 + p];
        if (tid < 64) zc += gp[4096 + tid];
    }

    // per-CTA constants (one 8-wide block reduce; also makes tiles visible)
    float Cwx, Cwx2, Cwxwy, Cwy, Cwy2, Czpx2, Czpxzpy, Czpy2;
    {
        float cv[8];
        cv[0]=cv[1]=cv[2]=cv[3]=cv[4]=0.f;
        #pragma unroll
        for (int i = 0; i < 16; i++){
            cv[0] += wx[i];       cv[1] = fmaf(wx[i], wx[i], cv[1]);
            cv[2] = fmaf(wx[i], wy[i], cv[2]);
            cv[3] += wy[i];       cv[4] = fmaf(wy[i], wy[i], cv[4]);
        }
        cv[5] = zpxv*zpxv; cv[6] = zpxv*zpyv; cv[7] = zpyv*zpyv;  // 0 for tid>=64
        #pragma unroll
        for (int k = 0; k < 8; k++){
            #pragma unroll
            for (int o = 16; o; o >>= 1) cv[k] += __shfl_xor_sync(0xffffffffu, cv[k], o);
        }
        if (lane == 0){
            #pragma unroll
            for (int k = 0; k < 8; k++) cred[w*8 + k] = cv[k];
        }
        __syncthreads();
        float s[8];
        #pragma unroll
        for (int k = 0; k < 8; k++){
            float t = 0.f;
            #pragma unroll
            for (int w2 = 0; w2 < 8; w2++) t += cred[w2*8 + k];
            s[k] = t;
        }
        Cwx=s[0]; Cwx2=s[1]; Cwxwy=s[2]; Cwy=s[3]; Cwy2=s[4];
        Czpx2=s[5]; Czpxzpy=s[6]; Czpy2=s[7];
    }
    double dsum = 0.0, dsq = 0.0;
    const float inv4096 = 1.f/4096.f, inv64 = 1.f/64.f;

    #pragma unroll 1
    for (int r = 0; r < CHUNK; r++){
        const float4* z4p = (const float4*)&ztile[r*64 + d0];
        const float4* q4p = (const float4*)&qtile[r*64 + d0];
        float vv = vtile[r*64 + p];
        float sA = 0.f, sA2 = 0.f, sU = 0.f, sU2 = 0.f, sUwx = 0.f, sUwy = 0.f;
        float S1 = 0.f, S2 = 0.f, S3 = 0.f, S4 = 0.f, S5 = 0.f;
        #pragma unroll
        for (int j = 0; j < 4; j++){
            float4 z4 = z4p[j], q4 = q4p[j];
            float zz[4] = {z4.x, z4.y, z4.z, z4.w};
            float qq[4] = {q4.x, q4.y, q4.z, q4.w};
            #pragma unroll
            for (int c = 0; c < 4; c++){
                int i = j*4 + c;
                A[i] = fmaf(zz[c], vv, A[i]);
                float a = A[i];
                sA += a; sA2 = fmaf(a, a, sA2);
                float uu = a * wx[i];
                sU += uu; sU2 = fmaf(uu, uu, sU2);
                sUwx = fmaf(uu, wx[i], sUwx);
                sUwy = fmaf(uu, wy[i], sUwy);
                float qwz = qq[c] * wz[i];
                S1 = fmaf(qwz, uu, S1);
                S2 = fmaf(qwz, wx[i], S2);
                S3 = fmaf(qwz, wy[i], S3);
                S4 += qwz;
                S5 = fmaf(qq[c], ww[i], S5);
            }
        }
        float qv = 0.f, r6 = 0.f, r7 = 0.f, r8 = 0.f, r9 = 0.f, r10 = 0.f, r11 = 0.f;
        if (tid < 64){
            zc += ztile[r*64 + tid];
            qv = qtile[r*64 + tid];
            float y = zc * zpxv;
            r6 = zc; r7 = zc*zc; r8 = y*y; r9 = y*zpyv; r10 = y*zpxv; r11 = qv*qv;
        }
        #pragma unroll
        for (int o = 16; o; o >>= 1){
            sA   += __shfl_xor_sync(0xffffffffu, sA, o);
            sA2  += __shfl_xor_sync(0xffffffffu, sA2, o);
            sU   += __shfl_xor_sync(0xffffffffu, sU, o);
            sU2  += __shfl_xor_sync(0xffffffffu, sU2, o);
            sUwx += __shfl_xor_sync(0xffffffffu, sUwx, o);
            sUwy += __shfl_xor_sync(0xffffffffu, sUwy, o);
        }
        if (w < 2){
            #pragma unroll
            for (int o = 16; o; o >>= 1){
                r6  += __shfl_xor_sync(0xffffffffu, r6, o);
                r7  += __shfl_xor_sync(0xffffffffu, r7, o);
                r8  += __shfl_xor_sync(0xffffffffu, r8, o);
                r9  += __shfl_xor_sync(0xffffffffu, r9, o);
                r10 += __shfl_xor_sync(0xffffffffu, r10, o);
                r11 += __shfl_xor_sync(0xffffffffu, r11, o);
            }
        }
        if (lane == 0){
            red4[w][0] = make_float4(sA, sA2, sU, sU2);
            red4[w][1] = make_float4(sUwx, sUwy, r6, r7);
            red4[w][2] = make_float4(r8, r9, r10, r11);
        }
        __syncthreads();                                       // sync 1
        float4 a0 = red4[0][0], a1 = red4[0][1], a2v = red4[0][2];
        #pragma unroll
        for (int w2 = 1; w2 < 8; w2++){
            float4 t0 = red4[w2][0], t1 = red4[w2][1], t2 = red4[w2][2];
            a0.x += t0.x; a0.y += t0.y; a0.z += t0.z; a0.w += t0.w;
            a1.x += t1.x; a1.y += t1.y; a1.z += t1.z; a1.w += t1.w;
            a2v.x += t2.x; a2v.y += t2.y; a2v.z += t2.z; a2v.w += t2.w;
        }
        // scalar closed-forms
        float aBar = a0.x * inv4096;
        float ivs  = rsqrtf(a0.y*inv4096 - aBar*aBar + LN_EPS);
        float c0   = aBar * ivs;
        float Sst  = ivs*a0.z - c0*Cwx + Cwy;
        float Sst2 = ivs*ivs*a0.w + 2.f*ivs*(a1.y - c0*a1.x)
                   + Cwy2 - 2.f*c0*Cwxwy + c0*c0*Cwx2;
        float mzv  = a1.z * inv64;
        float ivz  = rsqrtf(a1.w*inv64 - mzv*mzv + LN_EPS);
        float dd0  = mzv * ivz;
        float Szt2 = ivz*ivz*a2v.x + 2.f*ivz*(a2v.y - dd0*a2v.z)
                   + Czpy2 - 2.f*dd0*Czpxzpy + dd0*dd0*Czpx2;
        float zn   = fmaxf(sqrtf(Szt2), 1e-8f);
        float izn  = 1.f / zn;
        float mst  = Sst * inv4096;
        float mnam = mst * izn;
        float vnam = (Sst2*inv4096 - mst*mst) * izn * izn;
        float ivn  = rsqrtf(vnam + LN_EPS);
        float k1   = izn * ivn, k0 = -mnam * ivn;
        float srq  = 1.f / fmaxf(sqrtf(a2v.w), 1e-8f);

        if (tid < 64){
            float zt = (zc - mzv)*ivz*zpxv + zpyv;
            float rr = qv / fmaxf(zt, 1e-6f);
            dsum += (double)rr; dsq += (double)rr * (double)rr;
        }

        // na contraction from precomputed q-moments (4 FMA)
        float f1 = k1 * ivs, f2 = -f1 * aBar, f3 = k1;
        float accn = fmaf(f1, S1, fmaf(f2, S2, fmaf(f3, S3, fmaf(k0, S4, S5))));
        na_part[tid] = accn;
        __syncthreads();                                       // sync 2

        if (tid < 32){
            float nvA = (na_part[lane] + na_part[lane+64] + na_part[lane+128] + na_part[lane+192]) * srq;
            float nvB = (na_part[lane+32] + na_part[lane+96] + na_part[lane+160] + na_part[lane+224]) * srq;
            float s1 = nvA + nvB, s2 = nvA*nvA + nvB*nvB;
            #pragma unroll
            for (int o = 16; o; o >>= 1){
                s1 += __shfl_xor_sync(0xffffffffu, s1, o);
                s2 += __shfl_xor_sync(0xffffffffu, s2, o);
            }
            float mn = s1 * inv64;
            float iv = rsqrtf(s2*inv64 - mn*mn + LN_EPS);
            float* op = out + base + (size_t)r*64;
            op[lane]      = (nvA - mn)*iv*ngA + nbA;
            op[lane + 32] = (nvB - mn)*iv*ngB + nbB;
        }
    }

    // reduce local double sums -> global
    __syncthreads();
    if (tid < 64){ db[tid] = dsum; db[64 + tid] = dsq; }
    __syncthreads();
    if (tid == 0){
        double a = 0.0, c = 0.0;
        for (int i = 0; i < 64; i++){ a += db[i]; c += db[64 + i]; }
        atomicAdd(&g_acc[0], a);
        atomicAdd(&g_acc[1], c);
    }
}

// ---------------- kernel E: finalize std ----------------
__global__ void k_std(float* out, int n, int outpos)
{
    double mean = g_acc[0] / (double)n;
    double var  = (g_acc[1] - g_acc[0]*mean) / (double)(n - 1);
    out[outpos] = (float)sqrt(var);
}

// ---------------- launch ----------------
extern "C" void kernel_launch(void* const* d_in, const int* in_sizes, int n_in,
                              void* d_out, int out_size)
{
    const int*   uid   = (const int*)  d_in[0];
    const float* X     = (const float*)d_in[1];
    const float* Pm    = (const float*)d_in[2];
    const float* Sm    = (const float*)d_in[3];
    const float* Wq    = (const float*)d_in[4];
    const float* bq    = (const float*)d_in[5];
    const float* Wk    = (const float*)d_in[6];
    const float* bk    = (const float*)d_in[7];
    const float* Wv    = (const float*)d_in[8];
    const float* bv    = (const float*)d_in[9];
    const float* zg    = (const float*)d_in[10];
    const float* zb    = (const float*)d_in[11];
    const float* sg    = (const float*)d_in[12];
    const float* sb    = (const float*)d_in[13];
    const float* ng    = (const float*)d_in[14];
    const float* nb    = (const float*)d_in[15];
    const float* nag   = (const float*)d_in[16];
    const float* nab   = (const float*)d_in[17];
    const float* pzbuf = (const float*)d_in[18];
    const float* psbuf = (const float*)d_in[19];
    float* out = (float*)d_out;

    int B   = in_sizes[0];
    int L   = in_sizes[1] / (B * 64);
    int NCH = L / CHUNK;
    int LP  = in_sizes[2] / (B * 64);
    int NPH = B * NCH;

    k_front<<<NPH + B, 256>>>(uid, X, Pm, Sm, Wq, bq, Wk, bk, Wv, bv,
                              zg, zb, sg, sb, ng, nb, pzbuf, psbuf, NCH, LP, NPH);
    k_main<<<NPH, 256>>>(zg, zb, nag, nab, out, NCH);
    k_std<<<1, 1>>>(out, B*L*64, out_size - 1);
}

// round 10
// speedup vs baseline: 1.0225x; 1.0225x over previous
#include <cuda_runtime.h>
#include <math.h>

#define EPS 1e-8f
#define LN_EPS 1e-5f
#define CHUNK 32

// ---------------- scratch (static __device__, no allocs) ----------------
__device__ __align__(16) float  g_q[16*512*64];
__device__ __align__(16) float  g_z[16*512*64];
__device__ __align__(16) float  g_v[16*512*64];
__device__ __align__(16) float  g_part[16*16*4160];
__device__ float4 g_pack[16*4096];      // {sg, sb+Ps_ln, ng, nb+Mprev_ln}
__device__ float  g_Pz[16*64];          // P_z_ln last step per batch
__device__ double g_acc[2];             // sum, sumsq for std

__device__ __forceinline__ float eluf(float x){ return x > 0.f ? x : (expf(x) - 1.f); }

// one-sync block reduce for 256 threads (8 warps). Results broadcast to ALL
// threads in out[]. red: >= 8*N floats.
template<int N>
__device__ __forceinline__ void block_reduce_b(const float* v, float* red, float* out){
    int lane = threadIdx.x & 31, w = threadIdx.x >> 5;
    #pragma unroll
    for (int i = 0; i < N; i++){
        float x = v[i];
        #pragma unroll
        for (int o = 16; o; o >>= 1) x += __shfl_xor_sync(0xffffffffu, x, o);
        if (lane == 0) red[w*N + i] = x;
    }
    __syncthreads();
    #pragma unroll
    for (int i = 0; i < N; i++){
        float s = 0.f;
        #pragma unroll
        for (int ww2 = 0; ww2 < 8; ww2++) s += red[ww2*N + i];
        out[i] = s;
    }
}

// ---------------- fused front kernel: prompt CTAs FIRST (blocks [0,B)),
// ---------------- phase1 GEMMs (blocks [B, B+B*NCH)) ----------------
__global__ __launch_bounds__(256)
void k_front(const int* uid, const float* X, const float* Pm, const float* Sm,
             const float* Wq, const float* bq, const float* Wk, const float* bk,
             const float* Wv, const float* bv,
             const float* zg, const float* zb, const float* sg, const float* sb,
             const float* ng, const float* nb,
             const float* pzbuf, const float* psbuf, int NCH, int LP, int B)
{
    __shared__ __align__(16) float SBUF[11360];
    int tid = threadIdx.x;

    if ((int)blockIdx.x >= B){
        // ---------------- phase1 branch ----------------
        float* xsT  = SBUF;            // 64*36 transposed X chunk
        float* zbuf = SBUF + 2304;     // 32*64
        float* vbuf = SBUF + 4352;     // 32*64

        int pid = blockIdx.x - B;
        int b = pid / NCH, ch = pid % NCH;
        int L = NCH * CHUNK;
        size_t xbase = ((size_t)b*L + (size_t)ch*CHUNK) * 64;

        #pragma unroll
        for (int i = 0; i < 8; i++){
            int e = tid + i*256;
            int l = e >> 6, k = e & 63;
            xsT[k*36 + l] = X[xbase + e];
        }
        __syncthreads();

        if (tid < 192){
            int dt = tid >> 6, col = tid & 63;
            const float* W = (dt == 0) ? Wq : ((dt == 1) ? Wk : Wv);
            float bb = (dt == 0) ? bq[col] : ((dt == 1) ? bk[col] : bv[col]);
            float acc32[32];
            #pragma unroll
            for (int l = 0; l < 32; l++) acc32[l] = bb;
            #pragma unroll 4
            for (int k = 0; k < 64; k++){
                float w = W[k*64 + col];
                const float4* xr = (const float4*)&xsT[k*36];
                #pragma unroll
                for (int lv = 0; lv < 8; lv++){
                    float4 x4 = xr[lv];
                    acc32[lv*4+0] = fmaf(x4.x, w, acc32[lv*4+0]);
                    acc32[lv*4+1] = fmaf(x4.y, w, acc32[lv*4+1]);
                    acc32[lv*4+2] = fmaf(x4.z, w, acc32[lv*4+2]);
                    acc32[lv*4+3] = fmaf(x4.w, w, acc32[lv*4+3]);
                }
            }
            if (dt == 0){
                #pragma unroll
                for (int l = 0; l < 32; l++) g_q[xbase + l*64 + col] = eluf(acc32[l]);
            } else if (dt == 1){
                #pragma unroll
                for (int l = 0; l < 32; l++){
                    float zv = eluf(acc32[l]);
                    zbuf[l*64 + col] = zv;
                    g_z[xbase + l*64 + col] = zv;
                }
            } else {
                #pragma unroll
                for (int l = 0; l < 32; l++){
                    vbuf[l*64 + col] = acc32[l];
                    g_v[xbase + l*64 + col] = acc32[l];
                }
            }
        }
        __syncthreads();

        int p = tid & 63, d0 = (tid >> 6) * 16;
        float acc[16];
        #pragma unroll
        for (int i = 0; i < 16; i++) acc[i] = 0.f;
        #pragma unroll 4
        for (int l = 0; l < 32; l++){
            float vv = vbuf[l*64 + p];
            const float4* zb4 = (const float4*)&zbuf[l*64 + d0];
            #pragma unroll
            for (int j = 0; j < 4; j++){
                float4 z4 = zb4[j];
                acc[j*4+0] = fmaf(z4.x, vv, acc[j*4+0]);
                acc[j*4+1] = fmaf(z4.y, vv, acc[j*4+1]);
                acc[j*4+2] = fmaf(z4.z, vv, acc[j*4+2]);
                acc[j*4+3] = fmaf(z4.w, vv, acc[j*4+3]);
            }
        }
        size_t o = (size_t)(b*NCH + ch) * 4160;
        #pragma unroll
        for (int i = 0; i < 16; i++) g_part[o + (d0 + i)*64 + p] = acc[i];
        if (tid < 64){
            float zs = 0.f;
            #pragma unroll 4
            for (int l = 0; l < 32; l++) zs += zbuf[l*64 + tid];
            g_part[o + 4096 + tid] = zs;
        }
        return;
    }

    // ---------------- prompt branch (launched first -> overlaps phase1) ----
    float* xsA  = SBUF;          float* xsB  = SBUF + 512;
    float* zbA  = SBUF + 1024;   float* zbB  = SBUF + 1536;
    float* vbA  = SBUF + 2048;   float* vbB  = SBUF + 2560;
    float* bufA = SBUF + 3072;   float* bufB = SBUF + 7168;
    float* zl   = SBUF + 11264;
    float* redA = SBUF + 11328;  float* redB = SBUF + 11344;

    int b = blockIdx.x;
    int p = tid & 63, d0 = (tid >> 6) * 16;

    if (b == 0 && tid == 0){ g_acc[0] = 0.0; g_acc[1] = 0.0; }

    for (int i = tid; i < 512; i += 256){ xsA[i] = 0.f; xsB[i] = 0.f; }
    for (int i = tid; i < LP*64; i += 256){
        xsA[i] = Pm[b*LP*64 + i];
        xsB[i] = Sm[b*LP*64 + i];
    }
    __syncthreads();

    {
        int pass = tid >> 7, dt = (tid >> 6) & 1, col = tid & 63;
        const float* xp = pass ? xsB : xsA;
        float* zp = pass ? zbB : zbA;
        float* vp = pass ? vbB : vbA;
        const float* W  = dt ? Wv : Wk;
        float bb = dt ? bv[col] : bk[col];
        float acc8[8];
        #pragma unroll
        for (int l = 0; l < 8; l++) acc8[l] = bb;
        #pragma unroll 4
        for (int k = 0; k < 64; k++){
            float w = W[k*64 + col];
            #pragma unroll
            for (int l = 0; l < 8; l++) acc8[l] += xp[l*64 + k] * w;
        }
        if (dt == 0){
            #pragma unroll
            for (int l = 0; l < 8; l++) zp[l*64 + col] = eluf(acc8[l]);
        } else {
            #pragma unroll
            for (int l = 0; l < 8; l++) vp[l*64 + col] = acc8[l];
        }
    }
    __syncthreads();

    float accP[16], accS[16];
    #pragma unroll
    for (int i = 0; i < 16; i++){ accP[i] = 0.f; accS[i] = 0.f; }
    for (int l = 0; l < LP; l++){
        float vvP = vbA[l*64 + p], vvS = vbB[l*64 + p];
        #pragma unroll
        for (int i = 0; i < 16; i++){
            accP[i] += zbA[l*64 + d0 + i] * vvP;
            accS[i] += zbB[l*64 + d0 + i] * vvS;
        }
    }
    float zsP = 0.f, zsS = 0.f;
    if (tid < 64){
        for (int l = 0; l < LP; l++){ zsP += zbA[l*64 + tid]; zsS += zbB[l*64 + tid]; }
    }

    float rv[2], out2[2];
    rv[0] = (tid < 64) ? zsP : 0.f; rv[1] = (tid < 64) ? zsP*zsP : 0.f;
    block_reduce_b<2>(rv, redA, out2);
    {
        float mz = out2[0]*(1.f/64.f);
        float ivz = rsqrtf(out2[1]*(1.f/64.f) - mz*mz + LN_EPS);
        if (tid < 64) g_Pz[b*64 + tid] = (zsP - mz)*ivz*zg[tid] + zb[tid];
    }
    rv[0] = (tid < 64) ? zsS : 0.f; rv[1] = (tid < 64) ? zsS*zsS : 0.f;
    block_reduce_b<2>(rv, redB, out2);
    {
        float mz = out2[0]*(1.f/64.f);
        float ivz = rsqrtf(out2[1]*(1.f/64.f) - mz*mz + LN_EPS);
        if (tid < 64) zl[tid] = (zsS - mz)*ivz*zg[tid] + zb[tid];
    }
    float sv[2];
    sv[0] = 0.f; sv[1] = 0.f;
    #pragma unroll
    for (int i = 0; i < 16; i++){ sv[0] += accP[i]; sv[1] += accP[i]*accP[i]; }
    block_reduce_b<2>(sv, redA, out2);
    {
        float ms = out2[0]*(1.f/4096.f);
        float ivs = rsqrtf(out2[1]*(1.f/4096.f) - ms*ms + LN_EPS);
        #pragma unroll
        for (int i = 0; i < 16; i++){
            int e = (d0 + i)*64 + p;
            bufA[e] = (accP[i] - ms)*ivs*sg[e] + sb[e];
        }
    }
    sv[0] = 0.f; sv[1] = 0.f;
    #pragma unroll
    for (int i = 0; i < 16; i++){ sv[0] += accS[i]; sv[1] += accS[i]*accS[i]; }
    block_reduce_b<2>(sv, redB, out2);
    {
        float ms = out2[0]*(1.f/4096.f);
        float ivs = rsqrtf(out2[1]*(1.f/4096.f) - ms*ms + LN_EPS);
        #pragma unroll
        for (int i = 0; i < 16; i++){
            int e = (d0 + i)*64 + p;
            bufB[e] = (accS[i] - ms)*ivs*sg[e] + sb[e];
        }
    }
    __syncthreads();

    int u = uid[b];
    float pzv = 0.f;
    if (tid < 64) pzv = pzbuf[(size_t)u*64 + tid] + zl[tid];
    float rv1[1], out1[1];
    rv1[0] = (tid < 64) ? pzv*pzv : 0.f;
    block_reduce_b<1>(rv1, redA, out1);
    float ipn = 1.f / (fmaxf(sqrtf(out1[0]), 1e-8f) + EPS);

    float pn16[16];
    sv[0] = 0.f; sv[1] = 0.f;
    #pragma unroll
    for (int k2 = 0; k2 < 16; k2++){
        int e = tid + k2*256;
        float pv = (psbuf[(size_t)u*4096 + e] + bufB[e]) * ipn;
        pn16[k2] = pv; sv[0] += pv; sv[1] += pv*pv;
    }
    block_reduce_b<2>(sv, redB, out2);
    float mp = out2[0]*(1.f/4096.f);
    float ivp = rsqrtf(out2[1]*(1.f/4096.f) - mp*mp + LN_EPS);
    #pragma unroll
    for (int k2 = 0; k2 < 16; k2++){
        int e = tid + k2*256;
        float M = (pn16[k2] - mp)*ivp*ng[e] + nb[e];
        g_pack[b*4096 + e] = make_float4(sg[e], sb[e] + bufA[e], ng[e], nb[e] + M);
    }
}

// ---------------- kernel D: main scan — 3-phase chunk design, 4 syncs TOTAL.
// Pass 1 (no syncs): evolve A, per-warp 12-moment shfl reduce -> mom table.
// Scalar phase: 32 threads, one step each -> per-step scalars.
// Pass 2 (no syncs, backward over r): recompute A_r by subtraction, emit
// na partials to na_s table + std accumulation. Epilogue: 8 warps x 4 steps.
__global__ __launch_bounds__(256, 2)
void k_main(const float* __restrict__ zg, const float* __restrict__ zb,
            const float* __restrict__ nag, const float* __restrict__ nab,
            float* __restrict__ out, int NCH)
{
    extern __shared__ __align__(16) float SM[];
    float*  ztile = SM;                     // 2048
    float*  vtile = SM + 2048;              // 2048
    float*  qtile = SM + 4096;              // 2048
    float4* mom4  = (float4*)(SM + 6144);   // 32*8*3 float4 = 3072 floats
    float4* scal4 = (float4*)(SM + 9216);   // 32*2 float4 = 256 floats
    float*  na_s  = SM + 9472;              // 8192
    float*  cred  = SM + 17664;             // 64
    double* db    = (double*)(SM + 17728);  // 128 doubles = 256 floats

    int tid = threadIdx.x;
    int b = blockIdx.x / NCH, ch = blockIdx.x % NCH;
    int lane = tid & 31, w = tid >> 5;
    int p = tid & 63, d0 = (tid >> 6) * 16;
    int L = NCH * CHUNK;
    size_t base = ((size_t)b*L + (size_t)ch*CHUNK) * 64;

    // preload whole chunk z/v/q tiles (float4)
    {
        const float4* gz4 = (const float4*)(g_z + base);
        const float4* gv4 = (const float4*)(g_v + base);
        const float4* gq4 = (const float4*)(g_q + base);
        float4* zt4 = (float4*)ztile; float4* vt4 = (float4*)vtile; float4* qt4 = (float4*)qtile;
        #pragma unroll
        for (int i = 0; i < 2; i++){
            int e = tid + i*256;
            zt4[e] = gz4[e]; vt4[e] = gv4[e]; qt4[e] = gq4[e];
        }
    }
    // packed constants -> registers
    float wx[16], wy[16], wz[16], ww[16];
    {
        const float4* pk = &g_pack[b*4096];
        #pragma unroll
        for (int i = 0; i < 16; i++){
            float4 t = pk[(d0 + i)*64 + p];
            wx[i] = t.x; wy[i] = t.y; wz[i] = t.z; ww[i] = t.w;
        }
    }
    float zpxv = 0.f, zpyv = 0.f;
    if (tid < 64){ zpxv = zg[tid]; zpyv = zb[tid] + g_Pz[b*64 + tid]; }
    float ngA = nag[lane], ngB = nag[lane+32];
    float nbA = nab[lane], nbB = nab[lane+32];

    // fused exclusive prefix over prior chunks' partials
    float A[16];
    #pragma unroll
    for (int i = 0; i < 16; i++) A[i] = 0.f;
    float zc = 0.f;
    for (int c2 = 0; c2 < ch; c2++){
        const float* gp = &g_part[(size_t)(b*NCH + c2) * 4160];
        #pragma unroll
        for (int i = 0; i < 16; i++) A[i] += gp[(d0 + i)*64 + p];
        if (tid < 64) zc += gp[4096 + tid];
    }

    // per-CTA constants (one 8-wide block reduce; also makes tiles visible)
    float Cwx, Cwx2, Cwxwy, Cwy, Cwy2, Czpx2, Czpxzpy, Czpy2;
    {
        float cv[8];
        cv[0]=cv[1]=cv[2]=cv[3]=cv[4]=0.f;
        #pragma unroll
        for (int i = 0; i < 16; i++){
            cv[0] += wx[i];       cv[1] = fmaf(wx[i], wx[i], cv[1]);
            cv[2] = fmaf(wx[i], wy[i], cv[2]);
            cv[3] += wy[i];       cv[4] = fmaf(wy[i], wy[i], cv[4]);
        }
        cv[5] = zpxv*zpxv; cv[6] = zpxv*zpyv; cv[7] = zpyv*zpyv;  // 0 for tid>=64
        #pragma unroll
        for (int k = 0; k < 8; k++){
            #pragma unroll
            for (int o = 16; o; o >>= 1) cv[k] += __shfl_xor_sync(0xffffffffu, cv[k], o);
        }
        if (lane == 0){
            #pragma unroll
            for (int k = 0; k < 8; k++) cred[w*8 + k] = cv[k];
        }
        __syncthreads();                                        // sync 1
        float s[8];
        #pragma unroll
        for (int k = 0; k < 8; k++){
            float t = 0.f;
            #pragma unroll
            for (int w2 = 0; w2 < 8; w2++) t += cred[w2*8 + k];
            s[k] = t;
        }
        Cwx=s[0]; Cwx2=s[1]; Cwxwy=s[2]; Cwy=s[3]; Cwy2=s[4];
        Czpx2=s[5]; Czpxzpy=s[6]; Czpy2=s[7];
    }
    const float inv4096 = 1.f/4096.f, inv64 = 1.f/64.f;

    // ================= PASS 1: moments, no syncs =================
    #pragma unroll 1
    for (int r = 0; r < CHUNK; r++){
        const float4* z4p = (const float4*)&ztile[r*64 + d0];
        float vv = vtile[r*64 + p];
        float sA = 0.f, sA2 = 0.f, sU = 0.f, sU2 = 0.f, sUwx = 0.f, sUwy = 0.f;
        #pragma unroll
        for (int j = 0; j < 4; j++){
            float4 z4 = z4p[j];
            float zz[4] = {z4.x, z4.y, z4.z, z4.w};
            #pragma unroll
            for (int c = 0; c < 4; c++){
                int i = j*4 + c;
                A[i] = fmaf(zz[c], vv, A[i]);
                float a = A[i];
                sA += a; sA2 = fmaf(a, a, sA2);
                float uu = a * wx[i];
                sU += uu; sU2 = fmaf(uu, uu, sU2);
                sUwx = fmaf(uu, wx[i], sUwx);
                sUwy = fmaf(uu, wy[i], sUwy);
            }
        }
        float r6 = 0.f, r7 = 0.f, r8 = 0.f, r9 = 0.f, r10 = 0.f, r11 = 0.f;
        if (tid < 64){
            zc += ztile[r*64 + tid];
            float qv = qtile[r*64 + tid];
            float y = zc * zpxv;
            r6 = zc; r7 = zc*zc; r8 = y*y; r9 = y*zpyv; r10 = y*zpxv; r11 = qv*qv;
        }
        #pragma unroll
        for (int o = 16; o; o >>= 1){
            sA   += __shfl_xor_sync(0xffffffffu, sA, o);
            sA2  += __shfl_xor_sync(0xffffffffu, sA2, o);
            sU   += __shfl_xor_sync(0xffffffffu, sU, o);
            sU2  += __shfl_xor_sync(0xffffffffu, sU2, o);
            sUwx += __shfl_xor_sync(0xffffffffu, sUwx, o);
            sUwy += __shfl_xor_sync(0xffffffffu, sUwy, o);
        }
        if (w < 2){
            #pragma unroll
            for (int o = 16; o; o >>= 1){
                r6  += __shfl_xor_sync(0xffffffffu, r6, o);
                r7  += __shfl_xor_sync(0xffffffffu, r7, o);
                r8  += __shfl_xor_sync(0xffffffffu, r8, o);
                r9  += __shfl_xor_sync(0xffffffffu, r9, o);
                r10 += __shfl_xor_sync(0xffffffffu, r10, o);
                r11 += __shfl_xor_sync(0xffffffffu, r11, o);
            }
        }
        if (lane == 0){
            int mbase = (r*8 + w)*3;
            mom4[mbase + 0] = make_float4(sA, sA2, sU, sU2);
            mom4[mbase + 1] = make_float4(sUwx, sUwy, r6, r7);
            mom4[mbase + 2] = make_float4(r8, r9, r10, r11);
        }
    }
    __syncthreads();                                           // sync 2

    // ================= SCALAR PHASE: thread tid<32 owns step tid =================
    if (tid < 32){
        int r = tid;
        float4 a0 = make_float4(0,0,0,0), a1 = a0, a2v = a0;
        #pragma unroll
        for (int w2 = 0; w2 < 8; w2++){
            int mbase = (r*8 + w2)*3;
            float4 t0 = mom4[mbase], t1 = mom4[mbase+1], t2 = mom4[mbase+2];
            a0.x += t0.x; a0.y += t0.y; a0.z += t0.z; a0.w += t0.w;
            a1.x += t1.x; a1.y += t1.y; a1.z += t1.z; a1.w += t1.w;
            a2v.x += t2.x; a2v.y += t2.y; a2v.z += t2.z; a2v.w += t2.w;
        }
        float aBar = a0.x * inv4096;
        float ivs  = rsqrtf(a0.y*inv4096 - aBar*aBar + LN_EPS);
        float c0   = aBar * ivs;
        float Sst  = ivs*a0.z - c0*Cwx + Cwy;
        float Sst2 = ivs*ivs*a0.w + 2.f*ivs*(a1.y - c0*a1.x)
                   + Cwy2 - 2.f*c0*Cwxwy + c0*c0*Cwx2;
        float mzv  = a1.z * inv64;
        float ivz  = rsqrtf(a1.w*inv64 - mzv*mzv + LN_EPS);
        float dd0  = mzv * ivz;
        float Szt2 = ivz*ivz*a2v.x + 2.f*ivz*(a2v.y - dd0*a2v.z)
                   + Czpy2 - 2.f*dd0*Czpxzpy + dd0*dd0*Czpx2;
        float zn   = fmaxf(sqrtf(Szt2), 1e-8f);
        float izn  = 1.f / zn;
        float mst  = Sst * inv4096;
        float mnam = mst * izn;
        float vnam = (Sst2*inv4096 - mst*mst) * izn * izn;
        float ivn  = rsqrtf(vnam + LN_EPS);
        float k1   = izn * ivn, k0 = -mnam * ivn;
        float srq  = 1.f / fmaxf(sqrtf(a2v.w), 1e-8f);
        float f1 = k1 * ivs, f2 = -f1 * aBar, f3 = k1;
        scal4[r*2 + 0] = make_float4(f1, f2, f3, k0);
        scal4[r*2 + 1] = make_float4(srq, mzv, ivz, 0.f);
    }
    __syncthreads();                                           // sync 3

    // ================= PASS 2: backward, no syncs =================
    double dsum = 0.0, dsq = 0.0;
    #pragma unroll 1
    for (int r = CHUNK - 1; r >= 0; r--){
        float4 s0 = scal4[r*2 + 0];
        const float4* z4p = (const float4*)&ztile[r*64 + d0];
        const float4* q4p = (const float4*)&qtile[r*64 + d0];
        float vv = vtile[r*64 + p];
        float accn = 0.f;
        #pragma unroll
        for (int j = 0; j < 4; j++){
            float4 z4 = z4p[j], q4 = q4p[j];
            float zz[4] = {z4.x, z4.y, z4.z, z4.w};
            float qq[4] = {q4.x, q4.y, q4.z, q4.w};
            #pragma unroll
            for (int c = 0; c < 4; c++){
                int i = j*4 + c;
                float uu = A[i] * wx[i];
                float aa = fmaf(s0.x, uu, s0.w);
                aa = fmaf(s0.y, wx[i], aa);
                aa = fmaf(s0.z, wy[i], aa);
                float t = fmaf(aa, wz[i], ww[i]);
                accn = fmaf(qq[c], t, accn);
                A[i] = fmaf(-zz[c], vv, A[i]);   // step back to A_{r-1}
            }
        }
        na_s[r*256 + tid] = accn;
        if (tid < 64){
            float4 s1 = scal4[r*2 + 1];
            float zt = (zc - s1.y)*s1.z*zpxv + zpyv;
            float rr = qtile[r*64 + tid] / fmaxf(zt, 1e-6f);
            dsum += (double)rr; dsq += (double)rr * (double)rr;
            zc -= ztile[r*64 + tid];
        }
    }
    if (tid < 64){ db[tid] = dsum; db[64 + tid] = dsq; }
    __syncthreads();                                           // sync 4

    // ================= EPILOGUE: warp w -> steps w*4 .. w*4+3 =================
    {
        #pragma unroll
        for (int rr = 0; rr < 4; rr++){
            int r = w*4 + rr;
            float srq = scal4[r*2 + 1].x;
            const float* np = &na_s[r*256];
            float nvA = (np[lane] + np[lane+64] + np[lane+128] + np[lane+192]) * srq;
            float nvB = (np[lane+32] + np[lane+96] + np[lane+160] + np[lane+224]) * srq;
            float s1 = nvA + nvB, s2 = nvA*nvA + nvB*nvB;
            #pragma unroll
            for (int o = 16; o; o >>= 1){
                s1 += __shfl_xor_sync(0xffffffffu, s1, o);
                s2 += __shfl_xor_sync(0xffffffffu, s2, o);
            }
            float mn = s1 * inv64;
            float iv = rsqrtf(s2*inv64 - mn*mn + LN_EPS);
            float* op = out + base + (size_t)r*64;
            op[lane]      = (nvA - mn)*iv*ngA + nbA;
            op[lane + 32] = (nvB - mn)*iv*ngB + nbB;
        }
    }
    if (tid == 0){
        double a = 0.0, c = 0.0;
        for (int i = 0; i < 64; i++){ a += db[i]; c += db[64 + i]; }
        atomicAdd(&g_acc[0], a);
        atomicAdd(&g_acc[1], c);
    }
}

// ---------------- kernel E: finalize std ----------------
__global__ void k_std(float* out, int n, int outpos)
{
    double mean = g_acc[0] / (double)n;
    double var  = (g_acc[1] - g_acc[0]*mean) / (double)(n - 1);
    out[outpos] = (float)sqrt(var);
}

// ---------------- launch ----------------
extern "C" void kernel_launch(void* const* d_in, const int* in_sizes, int n_in,
                              void* d_out, int out_size)
{
    const int*   uid   = (const int*)  d_in[0];
    const float* X     = (const float*)d_in[1];
    const float* Pm    = (const float*)d_in[2];
    const float* Sm    = (const float*)d_in[3];
    const float* Wq    = (const float*)d_in[4];
    const float* bq    = (const float*)d_in[5];
    const float* Wk    = (const float*)d_in[6];
    const float* bk    = (const float*)d_in[7];
    const float* Wv    = (const float*)d_in[8];
    const float* bv    = (const float*)d_in[9];
    const float* zg    = (const float*)d_in[10];
    const float* zb    = (const float*)d_in[11];
    const float* sg    = (const float*)d_in[12];
    const float* sb    = (const float*)d_in[13];
    const float* ng    = (const float*)d_in[14];
    const float* nb    = (const float*)d_in[15];
    const float* nag   = (const float*)d_in[16];
    const float* nab   = (const float*)d_in[17];
    const float* pzbuf = (const float*)d_in[18];
    const float* psbuf = (const float*)d_in[19];
    float* out = (float*)d_out;

    int B   = in_sizes[0];
    int L   = in_sizes[1] / (B * 64);
    int NCH = L / CHUNK;
    int LP  = in_sizes[2] / (B * 64);
    int NPH = B * NCH;

    size_t smMain = (size_t)(17728 + 256) * 4;   // ~72 KB dynamic
    cudaFuncSetAttribute(k_main, cudaFuncAttributeMaxDynamicSharedMemorySize, (int)smMain);

    k_front<<<B + NPH, 256>>>(uid, X, Pm, Sm, Wq, bq, Wk, bk, Wv, bv,
                              zg, zb, sg, sb, ng, nb, pzbuf, psbuf, NCH, LP, B);
    k_main<<<NPH, 256, smMain>>>(zg, zb, nag, nab, out, NCH);
    k_std<<<1, 1>>>(out, B*L*64, out_size - 1);
}

// round 11
// speedup vs baseline: 1.1221x; 1.0975x over previous
#include <cuda_runtime.h>
#include <math.h>

#define EPS 1e-8f
#define LN_EPS 1e-5f
#define CHUNK 32

typedef unsigned long long ull;

// ---------------- packed f32x2 helpers (sm_103a) ----------------
__device__ __forceinline__ ull pack2(float lo, float hi){
    ull r; asm("mov.b64 %0, {%1,%2};" : "=l"(r) : "f"(lo), "f"(hi)); return r;
}
__device__ __forceinline__ void unpack2(ull v, float &lo, float &hi){
    asm("mov.b64 {%0,%1}, %2;" : "=f"(lo), "=f"(hi) : "l"(v));
}
__device__ __forceinline__ ull ffma2(ull a, ull b, ull c){
    ull d; asm("fma.rn.f32x2 %0, %1, %2, %3;" : "=l"(d) : "l"(a), "l"(b), "l"(c)); return d;
}
__device__ __forceinline__ ull fmul2(ull a, ull b){
    ull d; asm("mul.rn.f32x2 %0, %1, %2;" : "=l"(d) : "l"(a), "l"(b)); return d;
}
__device__ __forceinline__ ull fadd2(ull a, ull b){
    ull d; asm("add.rn.f32x2 %0, %1, %2;" : "=l"(d) : "l"(a), "l"(b)); return d;
}
__device__ __forceinline__ float hsum2(ull v){ float lo, hi; unpack2(v, lo, hi); return lo + hi; }

// ---------------- scratch (static __device__, no allocs) ----------------
__device__ __align__(16) float  g_q[16*512*64];
__device__ __align__(16) float  g_z[16*512*64];
__device__ __align__(16) float  g_v[16*512*64];
__device__ __align__(16) float  g_part[16*16*4160];
__device__ float4 g_pack[16*4096];      // {sg, sb+Ps_ln, ng, nb+Mprev_ln}
__device__ float  g_Pz[16*64];          // P_z_ln last step per batch
__device__ double g_acc[2];             // sum, sumsq for std

__device__ __forceinline__ float eluf(float x){ return x > 0.f ? x : (expf(x) - 1.f); }

// one-sync block reduce for 256 threads (8 warps). Results broadcast to ALL
// threads in out[]. red: >= 8*N floats.
template<int N>
__device__ __forceinline__ void block_reduce_b(const float* v, float* red, float* out){
    int lane = threadIdx.x & 31, w = threadIdx.x >> 5;
    #pragma unroll
    for (int i = 0; i < N; i++){
        float x = v[i];
        #pragma unroll
        for (int o = 16; o; o >>= 1) x += __shfl_xor_sync(0xffffffffu, x, o);
        if (lane == 0) red[w*N + i] = x;
    }
    __syncthreads();
    #pragma unroll
    for (int i = 0; i < N; i++){
        float s = 0.f;
        #pragma unroll
        for (int ww2 = 0; ww2 < 8; ww2++) s += red[ww2*N + i];
        out[i] = s;
    }
}

// ---------------- fused front kernel: prompt CTAs FIRST (blocks [0,B)),
// ---------------- phase1 GEMMs (blocks [B, B+B*NCH)) ----------------
__global__ __launch_bounds__(256)
void k_front(const int* uid, const float* X, const float* Pm, const float* Sm,
             const float* Wq, const float* bq, const float* Wk, const float* bk,
             const float* Wv, const float* bv,
             const float* zg, const float* zb, const float* sg, const float* sb,
             const float* ng, const float* nb,
             const float* pzbuf, const float* psbuf, int NCH, int LP, int B)
{
    __shared__ __align__(16) float SBUF[11360];
    int tid = threadIdx.x;

    if ((int)blockIdx.x >= B){
        // ---------------- phase1 branch (packed f32x2) ----------------
        float* xsT  = SBUF;            // 64*36 transposed X chunk (pitch 36 = 144B, 16B aligned)
        float* zbuf = SBUF + 2304;     // 32*64
        float* vbuf = SBUF + 4352;     // 32*64

        int pid = blockIdx.x - B;
        int b = pid / NCH, ch = pid % NCH;
        int L = NCH * CHUNK;
        size_t xbase = ((size_t)b*L + (size_t)ch*CHUNK) * 64;

        #pragma unroll
        for (int i = 0; i < 8; i++){
            int e = tid + i*256;
            int l = e >> 6, k = e & 63;
            xsT[k*36 + l] = X[xbase + e];
        }
        __syncthreads();

        if (tid < 192){
            int dt = tid >> 6, col = tid & 63;
            const float* W = (dt == 0) ? Wq : ((dt == 1) ? Wk : Wv);
            float bb = (dt == 0) ? bq[col] : ((dt == 1) ? bk[col] : bv[col]);
            ull bb2 = pack2(bb, bb);
            ull acc2[16];                       // 16 pairs = 32 rows
            #pragma unroll
            for (int j = 0; j < 16; j++) acc2[j] = bb2;
            #pragma unroll 4
            for (int k = 0; k < 64; k++){
                float w = W[k*64 + col];
                ull wp = pack2(w, w);
                const ulonglong2* xr = (const ulonglong2*)&xsT[k*36];
                #pragma unroll
                for (int j4 = 0; j4 < 8; j4++){
                    ulonglong2 xx = xr[j4];
                    acc2[j4*2+0] = ffma2(xx.x, wp, acc2[j4*2+0]);
                    acc2[j4*2+1] = ffma2(xx.y, wp, acc2[j4*2+1]);
                }
            }
            if (dt == 0){
                #pragma unroll
                for (int j = 0; j < 16; j++){
                    float a, b2; unpack2(acc2[j], a, b2);
                    g_q[xbase + (2*j  )*64 + col] = eluf(a);
                    g_q[xbase + (2*j+1)*64 + col] = eluf(b2);
                }
            } else if (dt == 1){
                #pragma unroll
                for (int j = 0; j < 16; j++){
                    float a, b2; unpack2(acc2[j], a, b2);
                    float za = eluf(a), zb2 = eluf(b2);
                    zbuf[(2*j  )*64 + col] = za;  g_z[xbase + (2*j  )*64 + col] = za;
                    zbuf[(2*j+1)*64 + col] = zb2; g_z[xbase + (2*j+1)*64 + col] = zb2;
                }
            } else {
                #pragma unroll
                for (int j = 0; j < 16; j++){
                    float a, b2; unpack2(acc2[j], a, b2);
                    vbuf[(2*j  )*64 + col] = a;   g_v[xbase + (2*j  )*64 + col] = a;
                    vbuf[(2*j+1)*64 + col] = b2;  g_v[xbase + (2*j+1)*64 + col] = b2;
                }
            }
        }
        __syncthreads();

        int p = tid & 63, d0 = (tid >> 6) * 16;
        ull acc2o[8];
        #pragma unroll
        for (int j = 0; j < 8; j++) acc2o[j] = 0ull;
        #pragma unroll 4
        for (int l = 0; l < 32; l++){
            float vv = vbuf[l*64 + p];
            ull vvp = pack2(vv, vv);
            const ulonglong2* zb2p = (const ulonglong2*)&zbuf[l*64 + d0];
            #pragma unroll
            for (int j4 = 0; j4 < 4; j4++){
                ulonglong2 zz = zb2p[j4];
                acc2o[j4*2+0] = ffma2(zz.x, vvp, acc2o[j4*2+0]);
                acc2o[j4*2+1] = ffma2(zz.y, vvp, acc2o[j4*2+1]);
            }
        }
        size_t o = (size_t)(b*NCH + ch) * 4160;
        #pragma unroll
        for (int j = 0; j < 8; j++){
            float a, b2; unpack2(acc2o[j], a, b2);
            g_part[o + (d0 + 2*j  )*64 + p] = a;
            g_part[o + (d0 + 2*j+1)*64 + p] = b2;
        }
        if (tid < 64){
            float zs = 0.f;
            #pragma unroll 4
            for (int l = 0; l < 32; l++) zs += zbuf[l*64 + tid];
            g_part[o + 4096 + tid] = zs;
        }
        return;
    }

    // ---------------- prompt branch (launched first -> overlaps phase1) ----
    float* xsA  = SBUF;          float* xsB  = SBUF + 512;
    float* zbA  = SBUF + 1024;   float* zbB  = SBUF + 1536;
    float* vbA  = SBUF + 2048;   float* vbB  = SBUF + 2560;
    float* bufA = SBUF + 3072;   float* bufB = SBUF + 7168;
    float* zl   = SBUF + 11264;
    float* redA = SBUF + 11328;  float* redB = SBUF + 11344;

    int b = blockIdx.x;
    int p = tid & 63, d0 = (tid >> 6) * 16;

    if (b == 0 && tid == 0){ g_acc[0] = 0.0; g_acc[1] = 0.0; }

    for (int i = tid; i < 512; i += 256){ xsA[i] = 0.f; xsB[i] = 0.f; }
    for (int i = tid; i < LP*64; i += 256){
        xsA[i] = Pm[b*LP*64 + i];
        xsB[i] = Sm[b*LP*64 + i];
    }
    __syncthreads();

    {
        int pass = tid >> 7, dt = (tid >> 6) & 1, col = tid & 63;
        const float* xp = pass ? xsB : xsA;
        float* zp = pass ? zbB : zbA;
        float* vp = pass ? vbB : vbA;
        const float* W  = dt ? Wv : Wk;
        float bb = dt ? bv[col] : bk[col];
        float acc8[8];
        #pragma unroll
        for (int l = 0; l < 8; l++) acc8[l] = bb;
        #pragma unroll 4
        for (int k = 0; k < 64; k++){
            float w = W[k*64 + col];
            #pragma unroll
            for (int l = 0; l < 8; l++) acc8[l] += xp[l*64 + k] * w;
        }
        if (dt == 0){
            #pragma unroll
            for (int l = 0; l < 8; l++) zp[l*64 + col] = eluf(acc8[l]);
        } else {
            #pragma unroll
            for (int l = 0; l < 8; l++) vp[l*64 + col] = acc8[l];
        }
    }
    __syncthreads();

    float accP[16], accS[16];
    #pragma unroll
    for (int i = 0; i < 16; i++){ accP[i] = 0.f; accS[i] = 0.f; }
    for (int l = 0; l < LP; l++){
        float vvP = vbA[l*64 + p], vvS = vbB[l*64 + p];
        #pragma unroll
        for (int i = 0; i < 16; i++){
            accP[i] += zbA[l*64 + d0 + i] * vvP;
            accS[i] += zbB[l*64 + d0 + i] * vvS;
        }
    }
    float zsP = 0.f, zsS = 0.f;
    if (tid < 64){
        for (int l = 0; l < LP; l++){ zsP += zbA[l*64 + tid]; zsS += zbB[l*64 + tid]; }
    }

    float rv[2], out2[2];
    rv[0] = (tid < 64) ? zsP : 0.f; rv[1] = (tid < 64) ? zsP*zsP : 0.f;
    block_reduce_b<2>(rv, redA, out2);
    {
        float mz = out2[0]*(1.f/64.f);
        float ivz = rsqrtf(out2[1]*(1.f/64.f) - mz*mz + LN_EPS);
        if (tid < 64) g_Pz[b*64 + tid] = (zsP - mz)*ivz*zg[tid] + zb[tid];
    }
    rv[0] = (tid < 64) ? zsS : 0.f; rv[1] = (tid < 64) ? zsS*zsS : 0.f;
    block_reduce_b<2>(rv, redB, out2);
    {
        float mz = out2[0]*(1.f/64.f);
        float ivz = rsqrtf(out2[1]*(1.f/64.f) - mz*mz + LN_EPS);
        if (tid < 64) zl[tid] = (zsS - mz)*ivz*zg[tid] + zb[tid];
    }
    float sv[2];
    sv[0] = 0.f; sv[1] = 0.f;
    #pragma unroll
    for (int i = 0; i < 16; i++){ sv[0] += accP[i]; sv[1] += accP[i]*accP[i]; }
    block_reduce_b<2>(sv, redA, out2);
    {
        float ms = out2[0]*(1.f/4096.f);
        float ivs = rsqrtf(out2[1]*(1.f/4096.f) - ms*ms + LN_EPS);
        #pragma unroll
        for (int i = 0; i < 16; i++){
            int e = (d0 + i)*64 + p;
            bufA[e] = (accP[i] - ms)*ivs*sg[e] + sb[e];
        }
    }
    sv[0] = 0.f; sv[1] = 0.f;
    #pragma unroll
    for (int i = 0; i < 16; i++){ sv[0] += accS[i]; sv[1] += accS[i]*accS[i]; }
    block_reduce_b<2>(sv, redB, out2);
    {
        float ms = out2[0]*(1.f/4096.f);
        float ivs = rsqrtf(out2[1]*(1.f/4096.f) - ms*ms + LN_EPS);
        #pragma unroll
        for (int i = 0; i < 16; i++){
            int e = (d0 + i)*64 + p;
            bufB[e] = (accS[i] - ms)*ivs*sg[e] + sb[e];
        }
    }
    __syncthreads();

    int u = uid[b];
    float pzv = 0.f;
    if (tid < 64) pzv = pzbuf[(size_t)u*64 + tid] + zl[tid];
    float rv1[1], out1[1];
    rv1[0] = (tid < 64) ? pzv*pzv : 0.f;
    block_reduce_b<1>(rv1, redA, out1);
    float ipn = 1.f / (fmaxf(sqrtf(out1[0]), 1e-8f) + EPS);

    float pn16[16];
    sv[0] = 0.f; sv[1] = 0.f;
    #pragma unroll
    for (int k2 = 0; k2 < 16; k2++){
        int e = tid + k2*256;
        float pv = (psbuf[(size_t)u*4096 + e] + bufB[e]) * ipn;
        pn16[k2] = pv; sv[0] += pv; sv[1] += pv*pv;
    }
    block_reduce_b<2>(sv, redB, out2);
    float mp = out2[0]*(1.f/4096.f);
    float ivp = rsqrtf(out2[1]*(1.f/4096.f) - mp*mp + LN_EPS);
    #pragma unroll
    for (int k2 = 0; k2 < 16; k2++){
        int e = tid + k2*256;
        float M = (pn16[k2] - mp)*ivp*ng[e] + nb[e];
        g_pack[b*4096 + e] = make_float4(sg[e], sb[e] + bufA[e], ng[e], nb[e] + M);
    }
}

// ---------------- kernel D: main scan — 3-phase chunk design, packed f32x2
// math throughout (halves FMA-pipe instruction count), no FP64 in loops.
__global__ __launch_bounds__(256, 2)
void k_main(const float* __restrict__ zg, const float* __restrict__ zb,
            const float* __restrict__ nag, const float* __restrict__ nab,
            float* __restrict__ out, int NCH)
{
    extern __shared__ __align__(16) float SM[];
    float*  ztile = SM;                     // 2048
    float*  vtile = SM + 2048;              // 2048
    float*  qtile = SM + 4096;              // 2048
    float4* mom4  = (float4*)(SM + 6144);   // 32*8*3 float4 = 3072 floats
    float4* scal4 = (float4*)(SM + 9216);   // 32*2 float4 = 256 floats
    float*  na_s  = SM + 9472;              // 8192
    float*  cred  = SM + 17664;             // 64
    double* db    = (double*)(SM + 17728);  // 128 doubles = 256 floats

    int tid = threadIdx.x;
    int b = blockIdx.x / NCH, ch = blockIdx.x % NCH;
    int lane = tid & 31, w = tid >> 5;
    int p = tid & 63, d0 = (tid >> 6) * 16;
    int L = NCH * CHUNK;
    size_t base = ((size_t)b*L + (size_t)ch*CHUNK) * 64;

    // preload whole chunk z/v/q tiles (float4)
    {
        const float4* gz4 = (const float4*)(g_z + base);
        const float4* gv4 = (const float4*)(g_v + base);
        const float4* gq4 = (const float4*)(g_q + base);
        float4* zt4 = (float4*)ztile; float4* vt4 = (float4*)vtile; float4* qt4 = (float4*)qtile;
        #pragma unroll
        for (int i = 0; i < 2; i++){
            int e = tid + i*256;
            zt4[e] = gz4[e]; vt4[e] = gv4[e]; qt4[e] = gq4[e];
        }
    }
    // packed constants -> registers (pairs over adjacent i)
    ull wx2[8], wy2[8], wz2[8], ww2[8];
    {
        const float4* pk = &g_pack[b*4096];
        #pragma unroll
        for (int j = 0; j < 8; j++){
            float4 ta = pk[(d0 + 2*j    )*64 + p];
            float4 tb = pk[(d0 + 2*j + 1)*64 + p];
            wx2[j] = pack2(ta.x, tb.x);
            wy2[j] = pack2(ta.y, tb.y);
            wz2[j] = pack2(ta.z, tb.z);
            ww2[j] = pack2(ta.w, tb.w);
        }
    }
    float zpxv = 0.f, zpyv = 0.f;
    if (tid < 64){ zpxv = zg[tid]; zpyv = zb[tid] + g_Pz[b*64 + tid]; }
    float ngA = nag[lane], ngB = nag[lane+32];
    float nbA = nab[lane], nbB = nab[lane+32];

    // fused exclusive prefix over prior chunks' partials -> packed A2
    ull A2[8];
    float zc = 0.f;
    {
        float A[16];
        #pragma unroll
        for (int i = 0; i < 16; i++) A[i] = 0.f;
        for (int c2 = 0; c2 < ch; c2++){
            const float* gp = &g_part[(size_t)(b*NCH + c2) * 4160];
            #pragma unroll
            for (int i = 0; i < 16; i++) A[i] += gp[(d0 + i)*64 + p];
            if (tid < 64) zc += gp[4096 + tid];
        }
        #pragma unroll
        for (int j = 0; j < 8; j++) A2[j] = pack2(A[2*j], A[2*j+1]);
    }

    // per-CTA constants (packed sums; one block reduce; makes tiles visible)
    float Cwx, Cwx2, Cwxwy, Cwy, Cwy2, Czpx2, Czpxzpy, Czpy2;
    {
        ull c0p = 0ull, c1p = 0ull, c2p = 0ull, c3p = 0ull, c4p = 0ull;
        #pragma unroll
        for (int j = 0; j < 8; j++){
            c0p = fadd2(c0p, wx2[j]);
            c1p = ffma2(wx2[j], wx2[j], c1p);
            c2p = ffma2(wx2[j], wy2[j], c2p);
            c3p = fadd2(c3p, wy2[j]);
            c4p = ffma2(wy2[j], wy2[j], c4p);
        }
        float cv[8];
        cv[0] = hsum2(c0p); cv[1] = hsum2(c1p); cv[2] = hsum2(c2p);
        cv[3] = hsum2(c3p); cv[4] = hsum2(c4p);
        cv[5] = zpxv*zpxv; cv[6] = zpxv*zpyv; cv[7] = zpyv*zpyv;  // 0 for tid>=64
        #pragma unroll
        for (int k = 0; k < 8; k++){
            #pragma unroll
            for (int o = 16; o; o >>= 1) cv[k] += __shfl_xor_sync(0xffffffffu, cv[k], o);
        }
        if (lane == 0){
            #pragma unroll
            for (int k = 0; k < 8; k++) cred[w*8 + k] = cv[k];
        }
        __syncthreads();                                        // sync 1
        float s[8];
        #pragma unroll
        for (int k = 0; k < 8; k++){
            float t = 0.f;
            #pragma unroll
            for (int w2 = 0; w2 < 8; w2++) t += cred[w2*8 + k];
            s[k] = t;
        }
        Cwx=s[0]; Cwx2=s[1]; Cwxwy=s[2]; Cwy=s[3]; Cwy2=s[4];
        Czpx2=s[5]; Czpxzpy=s[6]; Czpy2=s[7];
    }
    const float inv4096 = 1.f/4096.f, inv64 = 1.f/64.f;

    // ================= PASS 1: moments (packed), no syncs =================
    #pragma unroll 1
    for (int r = 0; r < CHUNK; r++){
        const ulonglong2* z2p = (const ulonglong2*)&ztile[r*64 + d0];
        float vv = vtile[r*64 + p];
        ull vv2 = pack2(vv, vv);
        ull pS = 0ull, pS2 = 0ull, pU = 0ull, pU2 = 0ull, pUwx = 0ull, pUwy = 0ull;
        #pragma unroll
        for (int j4 = 0; j4 < 4; j4++){
            ulonglong2 zz = z2p[j4];
            #pragma unroll
            for (int c = 0; c < 2; c++){
                int j = j4*2 + c;
                ull zp = c ? zz.y : zz.x;
                A2[j] = ffma2(zp, vv2, A2[j]);
                pS  = fadd2(pS, A2[j]);
                pS2 = ffma2(A2[j], A2[j], pS2);
                ull uu = fmul2(A2[j], wx2[j]);
                pU   = fadd2(pU, uu);
                pU2  = ffma2(uu, uu, pU2);
                pUwx = ffma2(uu, wx2[j], pUwx);
                pUwy = ffma2(uu, wy2[j], pUwy);
            }
        }
        float sA = hsum2(pS),  sA2 = hsum2(pS2), sU = hsum2(pU);
        float sU2 = hsum2(pU2), sUwx = hsum2(pUwx), sUwy = hsum2(pUwy);

        float r6 = 0.f, r7 = 0.f, r8 = 0.f, r9 = 0.f, r10 = 0.f, r11 = 0.f;
        if (tid < 64){
            zc += ztile[r*64 + tid];
            float qv = qtile[r*64 + tid];
            float y = zc * zpxv;
            r6 = zc; r7 = zc*zc; r8 = y*y; r9 = y*zpyv; r10 = y*zpxv; r11 = qv*qv;
        }
        #pragma unroll
        for (int o = 16; o; o >>= 1){
            sA   += __shfl_xor_sync(0xffffffffu, sA, o);
            sA2  += __shfl_xor_sync(0xffffffffu, sA2, o);
            sU   += __shfl_xor_sync(0xffffffffu, sU, o);
            sU2  += __shfl_xor_sync(0xffffffffu, sU2, o);
            sUwx += __shfl_xor_sync(0xffffffffu, sUwx, o);
            sUwy += __shfl_xor_sync(0xffffffffu, sUwy, o);
        }
        if (w < 2){
            #pragma unroll
            for (int o = 16; o; o >>= 1){
                r6  += __shfl_xor_sync(0xffffffffu, r6, o);
                r7  += __shfl_xor_sync(0xffffffffu, r7, o);
                r8  += __shfl_xor_sync(0xffffffffu, r8, o);
                r9  += __shfl_xor_sync(0xffffffffu, r9, o);
                r10 += __shfl_xor_sync(0xffffffffu, r10, o);
                r11 += __shfl_xor_sync(0xffffffffu, r11, o);
            }
        }
        if (lane == 0){
            int mbase = (r*8 + w)*3;
            mom4[mbase + 0] = make_float4(sA, sA2, sU, sU2);
            mom4[mbase + 1] = make_float4(sUwx, sUwy, r6, r7);
            mom4[mbase + 2] = make_float4(r8, r9, r10, r11);
        }
    }
    __syncthreads();                                           // sync 2

    // ================= SCALAR PHASE: thread tid<32 owns step tid =================
    if (tid < 32){
        int r = tid;
        float4 a0 = make_float4(0,0,0,0), a1 = a0, a2v = a0;
        #pragma unroll
        for (int w2 = 0; w2 < 8; w2++){
            int mbase = (r*8 + w2)*3;
            float4 t0 = mom4[mbase], t1 = mom4[mbase+1], t2 = mom4[mbase+2];
            a0.x += t0.x; a0.y += t0.y; a0.z += t0.z; a0.w += t0.w;
            a1.x += t1.x; a1.y += t1.y; a1.z += t1.z; a1.w += t1.w;
            a2v.x += t2.x; a2v.y += t2.y; a2v.z += t2.z; a2v.w += t2.w;
        }
        float aBar = a0.x * inv4096;
        float ivs  = rsqrtf(a0.y*inv4096 - aBar*aBar + LN_EPS);
        float c0   = aBar * ivs;
        float Sst  = ivs*a0.z - c0*Cwx + Cwy;
        float Sst2 = ivs*ivs*a0.w + 2.f*ivs*(a1.y - c0*a1.x)
                   + Cwy2 - 2.f*c0*Cwxwy + c0*c0*Cwx2;
        float mzv  = a1.z * inv64;
        float ivz  = rsqrtf(a1.w*inv64 - mzv*mzv + LN_EPS);
        float dd0  = mzv * ivz;
        float Szt2 = ivz*ivz*a2v.x + 2.f*ivz*(a2v.y - dd0*a2v.z)
                   + Czpy2 - 2.f*dd0*Czpxzpy + dd0*dd0*Czpx2;
        float zn   = fmaxf(sqrtf(Szt2), 1e-8f);
        float izn  = 1.f / zn;
        float mst  = Sst * inv4096;
        float mnam = mst * izn;
        float vnam = (Sst2*inv4096 - mst*mst) * izn * izn;
        float ivn  = rsqrtf(vnam + LN_EPS);
        float k1   = izn * ivn, k0 = -mnam * ivn;
        float srq  = 1.f / fmaxf(sqrtf(a2v.w), 1e-8f);
        float f1 = k1 * ivs, f2 = -f1 * aBar, f3 = k1;
        scal4[r*2 + 0] = make_float4(f1, f2, f3, k0);
        scal4[r*2 + 1] = make_float4(srq, mzv, ivz, 0.f);
    }
    __syncthreads();                                           // sync 3

    // ================= PASS 2: backward (packed), no syncs, no FP64 =========
    float fsum = 0.f, fsq = 0.f;
    #pragma unroll 1
    for (int r = CHUNK - 1; r >= 0; r--){
        float4 s0 = scal4[r*2 + 0];
        ull f1p = pack2(s0.x, s0.x), f2p = pack2(s0.y, s0.y);
        ull f3p = pack2(s0.z, s0.z), k0p = pack2(s0.w, s0.w);
        const ulonglong2* z2p = (const ulonglong2*)&ztile[r*64 + d0];
        const ulonglong2* q2p = (const ulonglong2*)&qtile[r*64 + d0];
        float vv = vtile[r*64 + p];
        ull nvv2 = pack2(-vv, -vv);
        ull pacc = 0ull;
        #pragma unroll
        for (int j4 = 0; j4 < 4; j4++){
            ulonglong2 zz = z2p[j4];
            ulonglong2 qq = q2p[j4];
            #pragma unroll
            for (int c = 0; c < 2; c++){
                int j = j4*2 + c;
                ull zp = c ? zz.y : zz.x;
                ull qp = c ? qq.y : qq.x;
                ull uu = fmul2(A2[j], wx2[j]);
                ull aa = ffma2(f1p, uu, k0p);
                aa = ffma2(f2p, wx2[j], aa);
                aa = ffma2(f3p, wy2[j], aa);
                ull t = ffma2(aa, wz2[j], ww2[j]);
                pacc = ffma2(qp, t, pacc);
                A2[j] = ffma2(zp, nvv2, A2[j]);    // step back to A_{r-1}
            }
        }
        na_s[r*256 + tid] = hsum2(pacc);
        if (tid < 64){
            float4 s1 = scal4[r*2 + 1];
            float zt = (zc - s1.y)*s1.z*zpxv + zpyv;
            float rr = qtile[r*64 + tid] / fmaxf(zt, 1e-6f);
            fsum += rr; fsq = fmaf(rr, rr, fsq);
            zc -= ztile[r*64 + tid];
        }
    }
    if (tid < 64){ db[tid] = (double)fsum; db[64 + tid] = (double)fsq; }
    __syncthreads();                                           // sync 4

    // ================= EPILOGUE: warp w -> steps w*4 .. w*4+3 =================
    {
        #pragma unroll
        for (int rr = 0; rr < 4; rr++){
            int r = w*4 + rr;
            float srq = scal4[r*2 + 1].x;
            const float* np = &na_s[r*256];
            float nvA = (np[lane] + np[lane+64] + np[lane+128] + np[lane+192]) * srq;
            float nvB = (np[lane+32] + np[lane+96] + np[lane+160] + np[lane+224]) * srq;
            float s1 = nvA + nvB, s2 = nvA*nvA + nvB*nvB;
            #pragma unroll
            for (int o = 16; o; o >>= 1){
                s1 += __shfl_xor_sync(0xffffffffu, s1, o);
                s2 += __shfl_xor_sync(0xffffffffu, s2, o);
            }
            float mn = s1 * inv64;
            float iv = rsqrtf(s2*inv64 - mn*mn + LN_EPS);
            float* op = out + base + (size_t)r*64;
            op[lane]      = (nvA - mn)*iv*ngA + nbA;
            op[lane + 32] = (nvB - mn)*iv*ngB + nbB;
        }
    }
    if (tid == 0){
        double a = 0.0, c = 0.0;
        for (int i = 0; i < 64; i++){ a += db[i]; c += db[64 + i]; }
        atomicAdd(&g_acc[0], a);
        atomicAdd(&g_acc[1], c);
    }
}

// ---------------- kernel E: finalize std ----------------
__global__ void k_std(float* out, int n, int outpos)
{
    double mean = g_acc[0] / (double)n;
    double var  = (g_acc[1] - g_acc[0]*mean) / (double)(n - 1);
    out[outpos] = (float)sqrt(var);
}

// ---------------- launch ----------------
extern "C" void kernel_launch(void* const* d_in, const int* in_sizes, int n_in,
                              void* d_out, int out_size)
{
    const int*   uid   = (const int*)  d_in[0];
    const float* X     = (const float*)d_in[1];
    const float* Pm    = (const float*)d_in[2];
    const float* Sm    = (const float*)d_in[3];
    const float* Wq    = (const float*)d_in[4];
    const float* bq    = (const float*)d_in[5];
    const float* Wk    = (const float*)d_in[6];
    const float* bk    = (const float*)d_in[7];
    const float* Wv    = (const float*)d_in[8];
    const float* bv    = (const float*)d_in[9];
    const float* zg    = (const float*)d_in[10];
    const float* zb    = (const float*)d_in[11];
    const float* sg    = (const float*)d_in[12];
    const float* sb    = (const float*)d_in[13];
    const float* ng    = (const float*)d_in[14];
    const float* nb    = (const float*)d_in[15];
    const float* nag   = (const float*)d_in[16];
    const float* nab   = (const float*)d_in[17];
    const float* pzbuf = (const float*)d_in[18];
    const float* psbuf = (const float*)d_in[19];
    float* out = (float*)d_out;

    int B   = in_sizes[0];
    int L   = in_sizes[1] / (B * 64);
    int NCH = L / CHUNK;
    int LP  = in_sizes[2] / (B * 64);
    int NPH = B * NCH;

    size_t smMain = (size_t)(17728 + 256) * 4;   // ~72 KB dynamic
    cudaFuncSetAttribute(k_main, cudaFuncAttributeMaxDynamicSharedMemorySize, (int)smMain);

    k_front<<<B + NPH, 256>>>(uid, X, Pm, Sm, Wq, bq, Wk, bk, Wv, bv,
                              zg, zb, sg, sb, ng, nb, pzbuf, psbuf, NCH, LP, B);
    k_main<<<NPH, 256, smMain>>>(zg, zb, nag, nab, out, NCH);
    k_std<<<1, 1>>>(out, B*L*64, out_size - 1);
}